// round 14
// baseline (speedup 1.0000x reference)
#include <cuda_runtime.h>
#include <math.h>

#define H      1024
#define TSTEPS 2048
#define KOUT   64
#define NBLK   128     // = H/8, one block per 8 hidden units
#define NTHR   512     // 16 warps -> 32 gate rows (2 rows per warp)

// Scratch (device globals: no allocation allowed in kernel_launch)
__device__ float g_hs[TSTEPS * H];   // h_t history (consumed by the MLP pass)
// Broadcast ping-pong: 2 slots x 1024 u64 packets {tag:32 | h_bits:32}.
// STRONG (relaxed.gpu) ops: single-copy atomic per 8B element + per-location
// coherent (PTX memory model). Data+tag in ONE word -> no fences anywhere in
// the hot loop (R12: gpu-scope fences emit CCTL.IVALL L1-flushes, 4x loss).
// tag = step+1: zero-init never matches; cross-replay residue is benign
// (identical deterministic values).
__device__ __align__(16) unsigned long long g_bc64[2 * 1024];

// ---------- helpers ----------

__device__ __forceinline__ float2 ffma2(float2 a, float2 b, float2 c) {
    unsigned long long ua = *reinterpret_cast<unsigned long long*>(&a);
    unsigned long long ub = *reinterpret_cast<unsigned long long*>(&b);
    unsigned long long uc = *reinterpret_cast<unsigned long long*>(&c);
    unsigned long long ud;
    asm("fma.rn.f32x2 %0, %1, %2, %3;" : "=l"(ud) : "l"(ua), "l"(ub), "l"(uc));
    return *reinterpret_cast<float2*>(&ud);
}

__device__ __forceinline__ void ld_relaxed_2u64(const unsigned long long* p,
                                                unsigned long long& a,
                                                unsigned long long& b) {
    asm volatile("ld.relaxed.gpu.global.v2.u64 {%0,%1}, [%2];"
                 : "=l"(a), "=l"(b) : "l"(p) : "memory");
}

__device__ __forceinline__ void st_relaxed_u64(unsigned long long* p, unsigned long long v) {
    asm volatile("st.relaxed.gpu.global.u64 [%0], %1;" :: "l"(p), "l"(v) : "memory");
}

// Accurate sigmoid; uniform path so the gate warp never diverges
// (tanh(x) = 2*sigmoid(2x) - 1). R9-proven: rel_err 1.39e-7 end-to-end.
__device__ __forceinline__ float sigm(float x) { return 1.0f / (1.0f + expf(-x)); }

// ---------- persistent LSTM recurrence (R9 layout, 4-deep poll) ----------
//
// Block b owns hidden units [8b, 8b+8). Warp w (0..15) computes gate rows
// r0=2w, r1=2w+1 (local); global row R = (r>>3)*H + b*8 + (r&7); order i,f,g,o.
// Weights Wc = Wih+Whh in registers (2 rows x 8 float4/thread -- the proven
// register sweet spot; 4 rows/thread spills, column-split regresses).
// Cross-SM sync: consumers poll self-tagged STRONG packets, 4-deep pipelined.

__global__ void __launch_bounds__(NTHR, 1)
lstm_kernel(const float* __restrict__ z,
            const float* __restrict__ Wih,
            const float* __restrict__ Whh,
            const float* __restrict__ bih,
            const float* __restrict__ bhh)
{
    __shared__ __align__(16) float h_sm[H];
    __shared__ float gates_sm[32];

    const int tid = threadIdx.x;
    const int b   = blockIdx.x;
    const int w   = tid >> 5;
    const int l   = tid & 31;
    const int r0  = 2 * w;
    const int r1  = 2 * w + 1;
    const int R0  = (r0 >> 3) * H + b * 8 + (r0 & 7);
    const int R1  = (r1 >> 3) * H + b * 8 + (r1 & 7);

    // Stage z into h_sm (input of step 0).
    reinterpret_cast<float2*>(h_sm)[tid] = reinterpret_cast<const float2*>(z)[tid];
    __syncthreads();

    const float4* Wih4 = reinterpret_cast<const float4*>(Wih);
    const float4* Whh4 = reinterpret_cast<const float4*>(Whh);
    const float4* h4   = reinterpret_cast<const float4*>(h_sm);

    // Prologue: load Wih/Whh once; compute step-0 partials with Wih (h0=0),
    // keep Wc = Wih + Whh resident in registers for all later steps.
    float4 wc0[8], wc1[8];
    float2 a0 = make_float2(0.f, 0.f);
    float2 a1 = make_float2(0.f, 0.f);
#pragma unroll
    for (int i = 0; i < 8; i++) {
        const int c0i = R0 * (H / 4) + i * 32 + l;
        const int c1i = R1 * (H / 4) + i * 32 + l;
        float4 wi0 = Wih4[c0i], wh0 = Whh4[c0i];
        float4 wi1 = Wih4[c1i], wh1 = Whh4[c1i];
        float4 hv  = h4[i * 32 + l];
        a0 = ffma2(make_float2(wi0.x, wi0.y), make_float2(hv.x, hv.y), a0);
        a0 = ffma2(make_float2(wi0.z, wi0.w), make_float2(hv.z, hv.w), a0);
        a1 = ffma2(make_float2(wi1.x, wi1.y), make_float2(hv.x, hv.y), a1);
        a1 = ffma2(make_float2(wi1.z, wi1.w), make_float2(hv.z, hv.w), a1);
        wc0[i] = make_float4(wi0.x + wh0.x, wi0.y + wh0.y, wi0.z + wh0.z, wi0.w + wh0.w);
        wc1[i] = make_float4(wi1.x + wh1.x, wi1.y + wh1.y, wi1.z + wh1.z, wi1.w + wh1.w);
    }
    const float bc0 = bih[R0] + bhh[R0];
    const float bc1 = bih[R1] + bhh[R1];

    float c = 0.0f;   // cell state: live only in warp 0, lanes 0..7

    for (int t = 0; t < TSTEPS; t++) {
        if (t > 0) {
            // Poll own two packets of h_{t-1}: 4-deep pipelined 16B strong
            // loads (issue four generations back-to-back before checking --
            // detection lag after visibility ~ RT/4).
            const unsigned want = (unsigned)t;            // tag of step t-1
            const unsigned long long* s = g_bc64 + ((t - 1) & 1) * 1024 + 2 * tid;
            unsigned long long p0, p1, q0, q1, r0v, r1v, u0, u1;
            for (;;) {
                ld_relaxed_2u64(s, p0, p1);
                ld_relaxed_2u64(s, q0, q1);
                ld_relaxed_2u64(s, r0v, r1v);
                ld_relaxed_2u64(s, u0, u1);
                if ((unsigned)(p0 >> 32) == want && (unsigned)(p1 >> 32) == want) break;
                if ((unsigned)(q0 >> 32) == want && (unsigned)(q1 >> 32) == want) {
                    p0 = q0; p1 = q1; break;
                }
                if ((unsigned)(r0v >> 32) == want && (unsigned)(r1v >> 32) == want) {
                    p0 = r0v; p1 = r1v; break;
                }
                if ((unsigned)(u0 >> 32) == want && (unsigned)(u1 >> 32) == want) {
                    p0 = u0; p1 = u1; break;
                }
            }
            reinterpret_cast<float2*>(h_sm)[tid] =
                make_float2(__uint_as_float((unsigned)p0), __uint_as_float((unsigned)p1));
            __syncthreads();

            // Matvec: gates = Wc @ h (register weights, smem h, packed f32x2 FMA)
            a0 = make_float2(0.f, 0.f);
            a1 = make_float2(0.f, 0.f);
#pragma unroll
            for (int i = 0; i < 8; i++) {
                float4 hv = h4[i * 32 + l];
                a0 = ffma2(make_float2(wc0[i].x, wc0[i].y), make_float2(hv.x, hv.y), a0);
                a0 = ffma2(make_float2(wc0[i].z, wc0[i].w), make_float2(hv.z, hv.w), a0);
                a1 = ffma2(make_float2(wc1[i].x, wc1[i].y), make_float2(hv.x, hv.y), a1);
                a1 = ffma2(make_float2(wc1[i].z, wc1[i].w), make_float2(hv.z, hv.w), a1);
            }
        }

        // Warp reductions: two interleaved 5-level butterflies.
        float s0 = a0.x + a0.y;
        float s1 = a1.x + a1.y;
#pragma unroll
        for (int d = 16; d > 0; d >>= 1) {
            s0 += __shfl_xor_sync(0xffffffffu, s0, d);
            s1 += __shfl_xor_sync(0xffffffffu, s1, d);
        }
        if (l == 0) {
            gates_sm[r0] = s0 + bc0;
            gates_sm[r1] = s1 + bc1;
        }
        __syncthreads();

        // Gate combine: warp 0, one gate per lane; UNIFORM nonlinearity path
        // (tanh(x) = 2*sigmoid(2x)-1) -> single expf sequence, no divergence.
        if (w == 0) {
            float gval = gates_sm[l];
            const bool is_g = (l >= 16 && l < 24);     // tanh lanes
            float xin = is_g ? 2.0f * gval : gval;
            float sg  = 1.0f / (1.0f + expf(-xin));
            float nl  = is_g ? fmaf(2.0f, sg, -1.0f) : sg;
            const int k = l & 7;
            float gi = __shfl_sync(0xffffffffu, nl, k);
            float gf = __shfl_sync(0xffffffffu, nl, 8 + k);
            float gg = __shfl_sync(0xffffffffu, nl, 16 + k);
            float go = __shfl_sync(0xffffffffu, nl, 24 + k);
            if (l < 8) {
                c = gf * c + gi * gg;
                float h = go * tanhf(c);

                // Packet out first (critical path), history store after.
                unsigned long long pkt =
                    ((unsigned long long)(unsigned)(t + 1) << 32) |
                    (unsigned long long)__float_as_uint(h);
                st_relaxed_u64(g_bc64 + (t & 1) * 1024 + b * 8 + l, pkt);
                g_hs[(size_t)t * H + b * 8 + l] = h;
            }
        }
        // Hold all warps until the local publish is issued: prevents 15 warps
        // from flooding L2 with stale polls while producers commit stores.
        __syncthreads();
    }
}

// ---------- per-timestep MLP head (R1's proven version) ----------

__global__ void __launch_bounds__(128)
mlp_kernel(const float* __restrict__ W1, const float* __restrict__ b1,
           const float* __restrict__ W2, const float* __restrict__ b2,
           const float* __restrict__ W3, const float* __restrict__ b3,
           float* __restrict__ out)
{
    __shared__ __align__(16) float h_sm[H];
    __shared__ float a1s[32];
    __shared__ float a2s[32];

    const int t   = blockIdx.x;
    const int tid = threadIdx.x;
    const int w   = tid >> 5;
    const int l   = tid & 31;

    const float4* src = reinterpret_cast<const float4*>(g_hs + (size_t)t * H);
    reinterpret_cast<float4*>(h_sm)[tid]       = src[tid];
    reinterpret_cast<float4*>(h_sm)[128 + tid] = src[128 + tid];
    __syncthreads();

    // Layer 1: 32 outputs; warp w computes outputs [8w, 8w+8), lanes stride columns.
    float acc[8];
#pragma unroll
    for (int oo = 0; oo < 8; oo++) acc[oo] = 0.0f;
#pragma unroll 4
    for (int i = 0; i < 32; i++) {
        float hv = h_sm[i * 32 + l];
#pragma unroll
        for (int oo = 0; oo < 8; oo++) {
            acc[oo] = fmaf(W1[(w * 8 + oo) * H + i * 32 + l], hv, acc[oo]);
        }
    }
#pragma unroll
    for (int oo = 0; oo < 8; oo++) {
#pragma unroll
        for (int d = 16; d > 0; d >>= 1)
            acc[oo] += __shfl_xor_sync(0xffffffffu, acc[oo], d);
    }
    if (l == 0) {
#pragma unroll
        for (int oo = 0; oo < 8; oo++) {
            int o = w * 8 + oo;
            a1s[o] = fmaxf(acc[oo] + b1[o], 0.0f);
        }
    }
    __syncthreads();

    // Layer 2: 32x32
    if (tid < 32) {
        float a = b2[tid];
#pragma unroll
        for (int k = 0; k < 32; k++) a = fmaf(W2[tid * 32 + k], a1s[k], a);
        a2s[tid] = fmaxf(a, 0.0f);
    }
    __syncthreads();

    // Layer 3: 64x32 -> output
    if (tid < KOUT) {
        float a = b3[tid];
#pragma unroll
        for (int k = 0; k < 32; k++) a = fmaf(W3[tid * 32 + k], a2s[k], a);
        out[(size_t)t * KOUT + tid] = a;
    }
}

// ---------- launch ----------

extern "C" void kernel_launch(void* const* d_in, const int* in_sizes, int n_in,
                              void* d_out, int out_size)
{
    const float* z   = (const float*)d_in[0];
    const float* Wih = (const float*)d_in[1];
    const float* Whh = (const float*)d_in[2];
    const float* bih = (const float*)d_in[3];
    const float* bhh = (const float*)d_in[4];
    const float* W1  = (const float*)d_in[5];
    const float* b1  = (const float*)d_in[6];
    const float* W2  = (const float*)d_in[7];
    const float* b2  = (const float*)d_in[8];
    const float* W3  = (const float*)d_in[9];
    const float* b3  = (const float*)d_in[10];
    float* out = (float*)d_out;

    lstm_kernel<<<NBLK, NTHR>>>(z, Wih, Whh, bih, bhh);
    mlp_kernel<<<TSTEPS, 128>>>(W1, b1, W2, b2, W3, b3, out);
}

// round 15
// speedup vs baseline: 1.1597x; 1.1597x over previous
#include <cuda_runtime.h>
#include <math.h>

#define H      1024
#define TSTEPS 2048
#define KOUT   64
#define NBLK   128     // = H/8, one block per 8 hidden units (+1 monitor block)
#define NTHR   512     // 16 warps -> 32 gate rows (2 rows per warp)

// Scratch (device globals: no allocation allowed in kernel_launch)
__device__ float g_hs[TSTEPS * H];   // h_t history (consumed by the MLP pass)
// Broadcast ping-pong: 2 slots x 1024 u64 packets {tag:32 | h_bits:32}.
// STRONG (relaxed.gpu) ops: single-copy atomic per 8B element + per-location
// coherent. Data+tag in ONE word -> no fences anywhere (R12: gpu-scope fences
// emit CCTL.IVALL L1-flushes, 4x loss). tag = step+1.
__device__ __align__(16) unsigned long long g_bc64[2 * 1024];
// Advisory readiness flags (ping-pong), written by the monitor block when all
// 1024 tags of a slot match. PURELY advisory: consumers still validate every
// packet tag, so flag staleness can only cost time, never correctness.
__device__ unsigned long long g_flag[2];

// ---------- helpers ----------

__device__ __forceinline__ float2 ffma2(float2 a, float2 b, float2 c) {
    unsigned long long ua = *reinterpret_cast<unsigned long long*>(&a);
    unsigned long long ub = *reinterpret_cast<unsigned long long*>(&b);
    unsigned long long uc = *reinterpret_cast<unsigned long long*>(&c);
    unsigned long long ud;
    asm("fma.rn.f32x2 %0, %1, %2, %3;" : "=l"(ud) : "l"(ua), "l"(ub), "l"(uc));
    return *reinterpret_cast<float2*>(&ud);
}

__device__ __forceinline__ unsigned long long ld_relaxed_u64(const unsigned long long* p) {
    unsigned long long v;
    asm volatile("ld.relaxed.gpu.global.u64 %0, [%1];" : "=l"(v) : "l"(p) : "memory");
    return v;
}

__device__ __forceinline__ void ld_relaxed_2u64(const unsigned long long* p,
                                                unsigned long long& a,
                                                unsigned long long& b) {
    asm volatile("ld.relaxed.gpu.global.v2.u64 {%0,%1}, [%2];"
                 : "=l"(a), "=l"(b) : "l"(p) : "memory");
}

__device__ __forceinline__ void st_relaxed_u64(unsigned long long* p, unsigned long long v) {
    asm volatile("st.relaxed.gpu.global.u64 [%0], %1;" :: "l"(p), "l"(v) : "memory");
}

// ---------- persistent LSTM recurrence (R9 layout + monitor flag) ----------
//
// Blocks 0..127: block b owns hidden units [8b, 8b+8). Warp w (0..15) computes
// gate rows r0=2w, r1=2w+1; global row R = (r>>3)*H + b*8 + (r&7); order i,f,g,o.
// Weights Wc = Wih+Whh in registers (2 rows x 8 float4/thread -- proven sweet
// spot; 4 rows spills, column-split regresses).
// Block 128 (monitor): spins on all 1024 packet tags (8KB/generation, ONE
// block), publishes advisory g_flag. Worker blocks poll the flag with a single
// thread -> chip-wide poll traffic drops ~100x vs direct polling (R14 showed
// poll traffic is the binding constraint).

__global__ void __launch_bounds__(NTHR, 1)
lstm_kernel(const float* __restrict__ z,
            const float* __restrict__ Wih,
            const float* __restrict__ Whh,
            const float* __restrict__ bih,
            const float* __restrict__ bhh)
{
    const int tid = threadIdx.x;

    // ---- monitor block ----
    if (blockIdx.x == NBLK) {
        // For each consumer step t (1..2047): wait until all 1024 packets of
        // slot (t-1)&1 carry tag t, then store advisory flag value t.
        for (int t = 1; t < TSTEPS; t++) {
            const unsigned long long* s = g_bc64 + ((t - 1) & 1) * 1024 + 2 * tid;
            bool ok;
            do {
                unsigned long long p0, p1;
                ld_relaxed_2u64(s, p0, p1);
                ok = ((unsigned)(p0 >> 32) == (unsigned)t) &&
                     ((unsigned)(p1 >> 32) == (unsigned)t);
            } while (!__syncthreads_and(ok));
            if (tid == 0) st_relaxed_u64(&g_flag[(t - 1) & 1], (unsigned long long)t);
        }
        return;
    }

    __shared__ __align__(16) float h_sm[H];
    __shared__ float gates_sm[32];

    const int b   = blockIdx.x;
    const int w   = tid >> 5;
    const int l   = tid & 31;
    const int r0  = 2 * w;
    const int r1  = 2 * w + 1;
    const int R0  = (r0 >> 3) * H + b * 8 + (r0 & 7);
    const int R1  = (r1 >> 3) * H + b * 8 + (r1 & 7);

    // Stage z into h_sm (input of step 0).
    reinterpret_cast<float2*>(h_sm)[tid] = reinterpret_cast<const float2*>(z)[tid];
    __syncthreads();

    const float4* Wih4 = reinterpret_cast<const float4*>(Wih);
    const float4* Whh4 = reinterpret_cast<const float4*>(Whh);
    const float4* h4   = reinterpret_cast<const float4*>(h_sm);

    // Prologue: load Wih/Whh once; compute step-0 partials with Wih (h0=0),
    // keep Wc = Wih + Whh resident in registers for all later steps.
    float4 wc0[8], wc1[8];
    float2 a0 = make_float2(0.f, 0.f);
    float2 a1 = make_float2(0.f, 0.f);
#pragma unroll
    for (int i = 0; i < 8; i++) {
        const int c0i = R0 * (H / 4) + i * 32 + l;
        const int c1i = R1 * (H / 4) + i * 32 + l;
        float4 wi0 = Wih4[c0i], wh0 = Whh4[c0i];
        float4 wi1 = Wih4[c1i], wh1 = Whh4[c1i];
        float4 hv  = h4[i * 32 + l];
        a0 = ffma2(make_float2(wi0.x, wi0.y), make_float2(hv.x, hv.y), a0);
        a0 = ffma2(make_float2(wi0.z, wi0.w), make_float2(hv.z, hv.w), a0);
        a1 = ffma2(make_float2(wi1.x, wi1.y), make_float2(hv.x, hv.y), a1);
        a1 = ffma2(make_float2(wi1.z, wi1.w), make_float2(hv.z, hv.w), a1);
        wc0[i] = make_float4(wi0.x + wh0.x, wi0.y + wh0.y, wi0.z + wh0.z, wi0.w + wh0.w);
        wc1[i] = make_float4(wi1.x + wh1.x, wi1.y + wh1.y, wi1.z + wh1.z, wi1.w + wh1.w);
    }
    const float bc0 = bih[R0] + bhh[R0];
    const float bc1 = bih[R1] + bhh[R1];

    float c = 0.0f;   // cell state: live only in warp 0, lanes 0..7

    for (int t = 0; t < TSTEPS; t++) {
        if (t > 0) {
            // Advisory flag wait: ONE poller per block (no L2 flood, no
            // single-address hotspot: 128 pollers chip-wide).
            if (tid == 0) {
                const unsigned long long want = (unsigned long long)t;
                unsigned long long f0, f1;
                do {
                    f0 = ld_relaxed_u64(&g_flag[(t - 1) & 1]);
                    f1 = ld_relaxed_u64(&g_flag[(t - 1) & 1]);
                } while (f0 != want && f1 != want);
            }
            __syncthreads();   // flag barrier

            // Fetch own two packets ONCE; per-packet tag validation retained
            // (correctness anchor -- flag is advisory only).
            const unsigned want = (unsigned)t;
            const unsigned long long* s = g_bc64 + ((t - 1) & 1) * 1024 + 2 * tid;
            unsigned long long p0, p1;
            for (;;) {
                ld_relaxed_2u64(s, p0, p1);
                if ((unsigned)(p0 >> 32) == want && (unsigned)(p1 >> 32) == want) break;
            }
            reinterpret_cast<float2*>(h_sm)[tid] =
                make_float2(__uint_as_float((unsigned)p0), __uint_as_float((unsigned)p1));
            __syncthreads();   // barrier #1: h_sm staged

            // Matvec: gates = Wc @ h (register weights, smem h, packed f32x2 FMA)
            a0 = make_float2(0.f, 0.f);
            a1 = make_float2(0.f, 0.f);
#pragma unroll
            for (int i = 0; i < 8; i++) {
                float4 hv = h4[i * 32 + l];
                a0 = ffma2(make_float2(wc0[i].x, wc0[i].y), make_float2(hv.x, hv.y), a0);
                a0 = ffma2(make_float2(wc0[i].z, wc0[i].w), make_float2(hv.z, hv.w), a0);
                a1 = ffma2(make_float2(wc1[i].x, wc1[i].y), make_float2(hv.x, hv.y), a1);
                a1 = ffma2(make_float2(wc1[i].z, wc1[i].w), make_float2(hv.z, hv.w), a1);
            }
        }

        // Warp reductions: two interleaved 5-level butterflies.
        float s0 = a0.x + a0.y;
        float s1 = a1.x + a1.y;
#pragma unroll
        for (int d = 16; d > 0; d >>= 1) {
            s0 += __shfl_xor_sync(0xffffffffu, s0, d);
            s1 += __shfl_xor_sync(0xffffffffu, s1, d);
        }
        if (l == 0) {
            gates_sm[r0] = s0 + bc0;
            gates_sm[r1] = s1 + bc1;
        }
        __syncthreads();   // barrier #2: gates ready

        // Gate combine: warp 0, one gate per lane; UNIFORM nonlinearity path
        // (tanh(x) = 2*sigmoid(2x)-1) -> single expf sequence, no divergence.
        if (w == 0) {
            float gval = gates_sm[l];
            const bool is_g = (l >= 16 && l < 24);     // tanh lanes
            float xin = is_g ? 2.0f * gval : gval;
            float sg  = 1.0f / (1.0f + expf(-xin));
            float nl  = is_g ? fmaf(2.0f, sg, -1.0f) : sg;
            const int k = l & 7;
            float gi = __shfl_sync(0xffffffffu, nl, k);
            float gf = __shfl_sync(0xffffffffu, nl, 8 + k);
            float gg = __shfl_sync(0xffffffffu, nl, 16 + k);
            float go = __shfl_sync(0xffffffffu, nl, 24 + k);
            if (l < 8) {
                c = gf * c + gi * gg;
                float h = go * tanhf(c);

                // Packet out first (critical path), history store after.
                unsigned long long pkt =
                    ((unsigned long long)(unsigned)(t + 1) << 32) |
                    (unsigned long long)__float_as_uint(h);
                st_relaxed_u64(g_bc64 + (t & 1) * 1024 + b * 8 + l, pkt);
                g_hs[(size_t)t * H + b * 8 + l] = h;
            }
        }
        // No trailing barrier (flood it guarded against is gone -- consumers
        // are flag-gated). Hazard ordering: h_sm writes at t+1 happen after
        // the flag barrier, which every warp reaches after barrier #2 of step
        // t (all matvec reads done). gates_sm reuse at t+1 is written after
        // barrier #2 of t+1; warp 0 finished reading gates_sm before joining
        // the t+1 flag barrier. Both hazards ordered.
    }
}

// ---------- per-timestep MLP head (R1's proven version) ----------

__global__ void __launch_bounds__(128)
mlp_kernel(const float* __restrict__ W1, const float* __restrict__ b1,
           const float* __restrict__ W2, const float* __restrict__ b2,
           const float* __restrict__ W3, const float* __restrict__ b3,
           float* __restrict__ out)
{
    __shared__ __align__(16) float h_sm[H];
    __shared__ float a1s[32];
    __shared__ float a2s[32];

    const int t   = blockIdx.x;
    const int tid = threadIdx.x;
    const int w   = tid >> 5;
    const int l   = tid & 31;

    const float4* src = reinterpret_cast<const float4*>(g_hs + (size_t)t * H);
    reinterpret_cast<float4*>(h_sm)[tid]       = src[tid];
    reinterpret_cast<float4*>(h_sm)[128 + tid] = src[128 + tid];
    __syncthreads();

    // Layer 1: 32 outputs; warp w computes outputs [8w, 8w+8), lanes stride columns.
    float acc[8];
#pragma unroll
    for (int oo = 0; oo < 8; oo++) acc[oo] = 0.0f;
#pragma unroll 4
    for (int i = 0; i < 32; i++) {
        float hv = h_sm[i * 32 + l];
#pragma unroll
        for (int oo = 0; oo < 8; oo++) {
            acc[oo] = fmaf(W1[(w * 8 + oo) * H + i * 32 + l], hv, acc[oo]);
        }
    }
#pragma unroll
    for (int oo = 0; oo < 8; oo++) {
#pragma unroll
        for (int d = 16; d > 0; d >>= 1)
            acc[oo] += __shfl_xor_sync(0xffffffffu, acc[oo], d);
    }
    if (l == 0) {
#pragma unroll
        for (int oo = 0; oo < 8; oo++) {
            int o = w * 8 + oo;
            a1s[o] = fmaxf(acc[oo] + b1[o], 0.0f);
        }
    }
    __syncthreads();

    // Layer 2: 32x32
    if (tid < 32) {
        float a = b2[tid];
#pragma unroll
        for (int k = 0; k < 32; k++) a = fmaf(W2[tid * 32 + k], a1s[k], a);
        a2s[tid] = fmaxf(a, 0.0f);
    }
    __syncthreads();

    // Layer 3: 64x32 -> output
    if (tid < KOUT) {
        float a = b3[tid];
#pragma unroll
        for (int k = 0; k < 32; k++) a = fmaf(W3[tid * 32 + k], a2s[k], a);
        out[(size_t)t * KOUT + tid] = a;
    }
}

// ---------- launch ----------

extern "C" void kernel_launch(void* const* d_in, const int* in_sizes, int n_in,
                              void* d_out, int out_size)
{
    const float* z   = (const float*)d_in[0];
    const float* Wih = (const float*)d_in[1];
    const float* Whh = (const float*)d_in[2];
    const float* bih = (const float*)d_in[3];
    const float* bhh = (const float*)d_in[4];
    const float* W1  = (const float*)d_in[5];
    const float* b1  = (const float*)d_in[6];
    const float* W2  = (const float*)d_in[7];
    const float* b2  = (const float*)d_in[8];
    const float* W3  = (const float*)d_in[9];
    const float* b3  = (const float*)d_in[10];
    float* out = (float*)d_out;

    lstm_kernel<<<NBLK + 1, NTHR>>>(z, Wih, Whh, bih, bhh);
    mlp_kernel<<<TSTEPS, 128>>>(W1, b1, W2, b2, W3, b3, out);
}

// round 16
// speedup vs baseline: 1.9937x; 1.7191x over previous
#include <cuda_runtime.h>
#include <math.h>

#define H      1024
#define TSTEPS 2048
#define KOUT   64
#define NBLK   128     // = H/8, one block per 8 hidden units
#define NTHR   512     // 16 warps -> 32 gate rows (2 rows per warp)

// Scratch (device globals: no allocation allowed in kernel_launch)
__device__ float g_hs[TSTEPS * H];   // h_t history (consumed by the MLP pass)
// Broadcast ping-pong: 2 slots x 1024 u64 packets {tag:32 | h_bits:32}.
// STRONG (relaxed.gpu) ops: single-copy atomic per 8B element + per-location
// coherent (PTX memory model). Data+tag in ONE word -> no fences anywhere in
// the hot loop (R12: gpu-scope fences emit CCTL.IVALL L1-flushes, 4x loss).
// tag = step+1: zero-init never matches; cross-replay residue is benign
// (identical deterministic values).
__device__ __align__(16) unsigned long long g_bc64[2 * 1024];

// ---------- helpers ----------

__device__ __forceinline__ float2 ffma2(float2 a, float2 b, float2 c) {
    unsigned long long ua = *reinterpret_cast<unsigned long long*>(&a);
    unsigned long long ub = *reinterpret_cast<unsigned long long*>(&b);
    unsigned long long uc = *reinterpret_cast<unsigned long long*>(&c);
    unsigned long long ud;
    asm("fma.rn.f32x2 %0, %1, %2, %3;" : "=l"(ud) : "l"(ua), "l"(ub), "l"(uc));
    return *reinterpret_cast<float2*>(&ud);
}

__device__ __forceinline__ void ld_relaxed_2u64(const unsigned long long* p,
                                                unsigned long long& a,
                                                unsigned long long& b) {
    asm volatile("ld.relaxed.gpu.global.v2.u64 {%0,%1}, [%2];"
                 : "=l"(a), "=l"(b) : "l"(p) : "memory");
}

__device__ __forceinline__ void st_relaxed_u64(unsigned long long* p, unsigned long long v) {
    asm volatile("st.relaxed.gpu.global.u64 [%0], %1;" :: "l"(p), "l"(v) : "memory");
}

// ---------- persistent LSTM recurrence (R9 layout, 1-deep poll) ----------
//
// Block b owns hidden units [8b, 8b+8). Warp w (0..15) computes gate rows
// r0=2w, r1=2w+1 (local); global row R = (r>>3)*H + b*8 + (r&7); order i,f,g,o.
// Weights Wc = Wih+Whh in registers (2 rows x 8 float4/thread -- the proven
// register sweet spot; 4 rows/thread spills, column-split regresses).
// Cross-SM sync: consumers poll self-tagged STRONG packets directly.
// POLL DEPTH = 1 (one 16B load per spin): R9(2-deep)=2896us, R14(4-deep)=
// 5135us -- time scales linearly with poll traffic, so halving traffic vs R9
// is predicted to cut ~1s of L2-queueing. One-variable experiment vs R9.

__global__ void __launch_bounds__(NTHR, 1)
lstm_kernel(const float* __restrict__ z,
            const float* __restrict__ Wih,
            const float* __restrict__ Whh,
            const float* __restrict__ bih,
            const float* __restrict__ bhh)
{
    __shared__ __align__(16) float h_sm[H];
    __shared__ float gates_sm[32];

    const int tid = threadIdx.x;
    const int b   = blockIdx.x;
    const int w   = tid >> 5;
    const int l   = tid & 31;
    const int r0  = 2 * w;
    const int r1  = 2 * w + 1;
    const int R0  = (r0 >> 3) * H + b * 8 + (r0 & 7);
    const int R1  = (r1 >> 3) * H + b * 8 + (r1 & 7);

    // Stage z into h_sm (input of step 0).
    reinterpret_cast<float2*>(h_sm)[tid] = reinterpret_cast<const float2*>(z)[tid];
    __syncthreads();

    const float4* Wih4 = reinterpret_cast<const float4*>(Wih);
    const float4* Whh4 = reinterpret_cast<const float4*>(Whh);
    const float4* h4   = reinterpret_cast<const float4*>(h_sm);

    // Prologue: load Wih/Whh once; compute step-0 partials with Wih (h0=0),
    // keep Wc = Wih + Whh resident in registers for all later steps.
    float4 wc0[8], wc1[8];
    float2 a0 = make_float2(0.f, 0.f);
    float2 a1 = make_float2(0.f, 0.f);
#pragma unroll
    for (int i = 0; i < 8; i++) {
        const int c0i = R0 * (H / 4) + i * 32 + l;
        const int c1i = R1 * (H / 4) + i * 32 + l;
        float4 wi0 = Wih4[c0i], wh0 = Whh4[c0i];
        float4 wi1 = Wih4[c1i], wh1 = Whh4[c1i];
        float4 hv  = h4[i * 32 + l];
        a0 = ffma2(make_float2(wi0.x, wi0.y), make_float2(hv.x, hv.y), a0);
        a0 = ffma2(make_float2(wi0.z, wi0.w), make_float2(hv.z, hv.w), a0);
        a1 = ffma2(make_float2(wi1.x, wi1.y), make_float2(hv.x, hv.y), a1);
        a1 = ffma2(make_float2(wi1.z, wi1.w), make_float2(hv.z, hv.w), a1);
        wc0[i] = make_float4(wi0.x + wh0.x, wi0.y + wh0.y, wi0.z + wh0.z, wi0.w + wh0.w);
        wc1[i] = make_float4(wi1.x + wh1.x, wi1.y + wh1.y, wi1.z + wh1.z, wi1.w + wh1.w);
    }
    const float bc0 = bih[R0] + bhh[R0];
    const float bc1 = bih[R1] + bhh[R1];

    float c = 0.0f;   // cell state: live only in warp 0, lanes 0..7

    for (int t = 0; t < TSTEPS; t++) {
        if (t > 0) {
            // Poll own two packets of h_{t-1}: ONE 16B strong load per spin
            // iteration (minimum possible poll traffic).
            const unsigned want = (unsigned)t;            // tag of step t-1
            const unsigned long long* s = g_bc64 + ((t - 1) & 1) * 1024 + 2 * tid;
            unsigned long long p0, p1;
            for (;;) {
                ld_relaxed_2u64(s, p0, p1);
                if ((unsigned)(p0 >> 32) == want && (unsigned)(p1 >> 32) == want) break;
            }
            reinterpret_cast<float2*>(h_sm)[tid] =
                make_float2(__uint_as_float((unsigned)p0), __uint_as_float((unsigned)p1));
            __syncthreads();

            // Matvec: gates = Wc @ h (register weights, smem h, packed f32x2 FMA)
            a0 = make_float2(0.f, 0.f);
            a1 = make_float2(0.f, 0.f);
#pragma unroll
            for (int i = 0; i < 8; i++) {
                float4 hv = h4[i * 32 + l];
                a0 = ffma2(make_float2(wc0[i].x, wc0[i].y), make_float2(hv.x, hv.y), a0);
                a0 = ffma2(make_float2(wc0[i].z, wc0[i].w), make_float2(hv.z, hv.w), a0);
                a1 = ffma2(make_float2(wc1[i].x, wc1[i].y), make_float2(hv.x, hv.y), a1);
                a1 = ffma2(make_float2(wc1[i].z, wc1[i].w), make_float2(hv.z, hv.w), a1);
            }
        }

        // Warp reductions: two interleaved 5-level butterflies.
        float s0 = a0.x + a0.y;
        float s1 = a1.x + a1.y;
#pragma unroll
        for (int d = 16; d > 0; d >>= 1) {
            s0 += __shfl_xor_sync(0xffffffffu, s0, d);
            s1 += __shfl_xor_sync(0xffffffffu, s1, d);
        }
        if (l == 0) {
            gates_sm[r0] = s0 + bc0;
            gates_sm[r1] = s1 + bc1;
        }
        __syncthreads();

        // Gate combine: warp 0, one gate per lane; UNIFORM nonlinearity path
        // (tanh(x) = 2*sigmoid(2x)-1) -> single expf sequence, no divergence.
        if (w == 0) {
            float gval = gates_sm[l];
            const bool is_g = (l >= 16 && l < 24);     // tanh lanes
            float xin = is_g ? 2.0f * gval : gval;
            float sg  = 1.0f / (1.0f + expf(-xin));
            float nl  = is_g ? fmaf(2.0f, sg, -1.0f) : sg;
            const int k = l & 7;
            float gi = __shfl_sync(0xffffffffu, nl, k);
            float gf = __shfl_sync(0xffffffffu, nl, 8 + k);
            float gg = __shfl_sync(0xffffffffu, nl, 16 + k);
            float go = __shfl_sync(0xffffffffu, nl, 24 + k);
            if (l < 8) {
                c = gf * c + gi * gg;
                float h = go * tanhf(c);

                // Packet out first (critical path), history store after.
                unsigned long long pkt =
                    ((unsigned long long)(unsigned)(t + 1) << 32) |
                    (unsigned long long)__float_as_uint(h);
                st_relaxed_u64(g_bc64 + (t & 1) * 1024 + b * 8 + l, pkt);
                g_hs[(size_t)t * H + b * 8 + l] = h;
            }
        }
        // Hold all warps until the local publish is issued: prevents 15 warps
        // from flooding L2 with stale polls while producers commit stores.
        __syncthreads();
    }
}

// ---------- per-timestep MLP head (R1's proven version) ----------

__global__ void __launch_bounds__(128)
mlp_kernel(const float* __restrict__ W1, const float* __restrict__ b1,
           const float* __restrict__ W2, const float* __restrict__ b2,
           const float* __restrict__ W3, const float* __restrict__ b3,
           float* __restrict__ out)
{
    __shared__ __align__(16) float h_sm[H];
    __shared__ float a1s[32];
    __shared__ float a2s[32];

    const int t   = blockIdx.x;
    const int tid = threadIdx.x;
    const int w   = tid >> 5;
    const int l   = tid & 31;

    const float4* src = reinterpret_cast<const float4*>(g_hs + (size_t)t * H);
    reinterpret_cast<float4*>(h_sm)[tid]       = src[tid];
    reinterpret_cast<float4*>(h_sm)[128 + tid] = src[128 + tid];
    __syncthreads();

    // Layer 1: 32 outputs; warp w computes outputs [8w, 8w+8), lanes stride columns.
    float acc[8];
#pragma unroll
    for (int oo = 0; oo < 8; oo++) acc[oo] = 0.0f;
#pragma unroll 4
    for (int i = 0; i < 32; i++) {
        float hv = h_sm[i * 32 + l];
#pragma unroll
        for (int oo = 0; oo < 8; oo++) {
            acc[oo] = fmaf(W1[(w * 8 + oo) * H + i * 32 + l], hv, acc[oo]);
        }
    }
#pragma unroll
    for (int oo = 0; oo < 8; oo++) {
#pragma unroll
        for (int d = 16; d > 0; d >>= 1)
            acc[oo] += __shfl_xor_sync(0xffffffffu, acc[oo], d);
    }
    if (l == 0) {
#pragma unroll
        for (int oo = 0; oo < 8; oo++) {
            int o = w * 8 + oo;
            a1s[o] = fmaxf(acc[oo] + b1[o], 0.0f);
        }
    }
    __syncthreads();

    // Layer 2: 32x32
    if (tid < 32) {
        float a = b2[tid];
#pragma unroll
        for (int k = 0; k < 32; k++) a = fmaf(W2[tid * 32 + k], a1s[k], a);
        a2s[tid] = fmaxf(a, 0.0f);
    }
    __syncthreads();

    // Layer 3: 64x32 -> output
    if (tid < KOUT) {
        float a = b3[tid];
#pragma unroll
        for (int k = 0; k < 32; k++) a = fmaf(W3[tid * 32 + k], a2s[k], a);
        out[(size_t)t * KOUT + tid] = a;
    }
}

// ---------- launch ----------

extern "C" void kernel_launch(void* const* d_in, const int* in_sizes, int n_in,
                              void* d_out, int out_size)
{
    const float* z   = (const float*)d_in[0];
    const float* Wih = (const float*)d_in[1];
    const float* Whh = (const float*)d_in[2];
    const float* bih = (const float*)d_in[3];
    const float* bhh = (const float*)d_in[4];
    const float* W1  = (const float*)d_in[5];
    const float* b1  = (const float*)d_in[6];
    const float* W2  = (const float*)d_in[7];
    const float* b2  = (const float*)d_in[8];
    const float* W3  = (const float*)d_in[9];
    const float* b3  = (const float*)d_in[10];
    float* out = (float*)d_out;

    lstm_kernel<<<NBLK, NTHR>>>(z, Wih, Whh, bih, bhh);
    mlp_kernel<<<TSTEPS, 128>>>(W1, b1, W2, b2, W3, b3, out);
}